// round 2
// baseline (speedup 1.0000x reference)
#include <cuda_runtime.h>

#define NB   8
#define NP   2048
#define C1   64
#define C2   128
#define NS   64
#define RAD2 0.36f

// Scratch: per-point MLP features f[b, n, 128]  (8 MB, fits L2)
__device__ float g_f[NB * NP * C2];

// ---------------------------------------------------------------------------
// Kernel 1: per-point MLP  f[p, :] = relu(W2 @ relu(W1 @ x[p] + b1) + b2)
// One warp per point. Lane computes h1 rows (lane, lane+32), then 4 output
// channels p0..p0+3 using shfl-broadcast of h1 and float4 W2 row loads (L1-hot).
// ---------------------------------------------------------------------------
__global__ __launch_bounds__(256)
void mlp_kernel(const float* __restrict__ x,
                const float* __restrict__ W1,
                const float* __restrict__ b1,
                const float* __restrict__ W2,
                const float* __restrict__ b2)
{
    int gw   = (blockIdx.x * 256 + threadIdx.x) >> 5;   // global warp = point id
    int lane = threadIdx.x & 31;
    if (gw >= NB * NP) return;

    float x0 = __ldg(&x[gw * 3 + 0]);
    float x1 = __ldg(&x[gw * 3 + 1]);
    float x2 = __ldg(&x[gw * 3 + 2]);

    // h1 rows lane and lane+32
    float ha = fmaf(__ldg(&W1[lane * 3 + 2]), x2,
               fmaf(__ldg(&W1[lane * 3 + 1]), x1,
               fmaf(__ldg(&W1[lane * 3 + 0]), x0, __ldg(&b1[lane]))));
    ha = fmaxf(ha, 0.f);
    int r = lane + 32;
    float hb = fmaf(__ldg(&W1[r * 3 + 2]), x2,
               fmaf(__ldg(&W1[r * 3 + 1]), x1,
               fmaf(__ldg(&W1[r * 3 + 0]), x0, __ldg(&b1[r]))));
    hb = fmaxf(hb, 0.f);

    int p0 = lane * 4;
    float a0 = __ldg(&b2[p0 + 0]);
    float a1 = __ldg(&b2[p0 + 1]);
    float a2 = __ldg(&b2[p0 + 2]);
    float a3 = __ldg(&b2[p0 + 3]);

    #pragma unroll
    for (int k4 = 0; k4 < C1; k4 += 4) {
        float h0 = __shfl_sync(0xffffffffu, (k4 + 0 < 32) ? ha : hb, (k4 + 0) & 31);
        float h1v = __shfl_sync(0xffffffffu, (k4 + 1 < 32) ? ha : hb, (k4 + 1) & 31);
        float h2v = __shfl_sync(0xffffffffu, (k4 + 2 < 32) ? ha : hb, (k4 + 2) & 31);
        float h3 = __shfl_sync(0xffffffffu, (k4 + 3 < 32) ? ha : hb, (k4 + 3) & 31);

        float4 w0 = *(const float4*)&W2[(p0 + 0) * C1 + k4];
        float4 w1 = *(const float4*)&W2[(p0 + 1) * C1 + k4];
        float4 w2 = *(const float4*)&W2[(p0 + 2) * C1 + k4];
        float4 w3 = *(const float4*)&W2[(p0 + 3) * C1 + k4];

        a0 = fmaf(h0, w0.x, fmaf(h1v, w0.y, fmaf(h2v, w0.z, fmaf(h3, w0.w, a0))));
        a1 = fmaf(h0, w1.x, fmaf(h1v, w1.y, fmaf(h2v, w1.z, fmaf(h3, w1.w, a1))));
        a2 = fmaf(h0, w2.x, fmaf(h1v, w2.y, fmaf(h2v, w2.z, fmaf(h3, w2.w, a2))));
        a3 = fmaf(h0, w3.x, fmaf(h1v, w3.y, fmaf(h2v, w3.z, fmaf(h3, w3.w, a3))));
    }

    float4 o;
    o.x = fmaxf(a0, 0.f);
    o.y = fmaxf(a1, 0.f);
    o.z = fmaxf(a2, 0.f);
    o.w = fmaxf(a3, 0.f);
    *(float4*)&g_f[gw * C2 + p0] = o;
}

// ---------------------------------------------------------------------------
// Kernel 2: ball query (first 64 in-radius indices, ascending) + max-pool of f.
// Block = 8 warps handles 8 centers of one batch. x/sq staged in SMEM.
// Each lane owns 4 output channels; accumulates fmax over neighbors via
// LDG.128 of f (L2-resident). Output transposed through padded SMEM so the
// (B,128,N) stores are 32B-sector contiguous.
// ---------------------------------------------------------------------------
__global__ __launch_bounds__(256)
void group_max_kernel(const float* __restrict__ x, float* __restrict__ out)
{
    __shared__ float xs[NP], ys[NP], zs[NP], sq[NP];     // 32 KB
    __shared__ unsigned short nbr[8][NS];                // 1 KB
    __shared__ float tr[8][132];                         // 4.1 KB, pad kills conflicts

    int b   = blockIdx.y;
    int tid = threadIdx.x;

    // Stage batch's coordinates + squared norms
    const float* xb = x + b * NP * 3;
    for (int i = tid; i < NP; i += 256) {
        float a0 = xb[i * 3 + 0];
        float a1 = xb[i * 3 + 1];
        float a2 = xb[i * 3 + 2];
        xs[i] = a0; ys[i] = a1; zs[i] = a2;
        sq[i] = a0 * a0 + a1 * a1 + a2 * a2;
    }
    __syncthreads();

    int warp = tid >> 5, lane = tid & 31;
    int s = blockIdx.x * 8 + warp;

    float cx = xs[s], cy = ys[s], cz = zs[s], cs = sq[s];

    // Scan j ascending; collect first <=64 indices with dist <= R^2
    int cnt = 0;
    for (int j0 = 0; j0 < NP && cnt < NS; j0 += 32) {
        int j = j0 + lane;
        float d = cs + sq[j] - 2.f * (cx * xs[j] + cy * ys[j] + cz * zs[j]);
        bool ok = !(d > RAD2);
        unsigned mask = __ballot_sync(0xffffffffu, ok);
        int rank = __popc(mask & ((1u << lane) - 1u));
        if (ok && (cnt + rank) < NS)
            nbr[warp][cnt + rank] = (unsigned short)j;
        cnt += __popc(mask);
        if (cnt > NS) cnt = NS;
    }
    __syncwarp();

    // Max-pool f over the neighbor list (4 channels per lane, unroll x4)
    const float* fb = g_f + (size_t)b * NP * C2 + lane * 4;
    float4 acc = {0.f, 0.f, 0.f, 0.f};   // post-relu values are >= 0
    int k = 0;
    for (; k + 4 <= cnt; k += 4) {
        int j0 = nbr[warp][k + 0];
        int j1 = nbr[warp][k + 1];
        int j2 = nbr[warp][k + 2];
        int j3 = nbr[warp][k + 3];
        float4 f0 = *(const float4*)&fb[j0 * C2];
        float4 f1 = *(const float4*)&fb[j1 * C2];
        float4 f2 = *(const float4*)&fb[j2 * C2];
        float4 f3 = *(const float4*)&fb[j3 * C2];
        acc.x = fmaxf(acc.x, fmaxf(fmaxf(f0.x, f1.x), fmaxf(f2.x, f3.x)));
        acc.y = fmaxf(acc.y, fmaxf(fmaxf(f0.y, f1.y), fmaxf(f2.y, f3.y)));
        acc.z = fmaxf(acc.z, fmaxf(fmaxf(f0.z, f1.z), fmaxf(f2.z, f3.z)));
        acc.w = fmaxf(acc.w, fmaxf(fmaxf(f0.w, f1.w), fmaxf(f2.w, f3.w)));
    }
    for (; k < cnt; k++) {
        int j = nbr[warp][k];
        float4 f0 = *(const float4*)&fb[j * C2];
        acc.x = fmaxf(acc.x, f0.x);
        acc.y = fmaxf(acc.y, f0.y);
        acc.z = fmaxf(acc.z, f0.z);
        acc.w = fmaxf(acc.w, f0.w);
    }

    // Transpose through SMEM: tr[warp][channel], then coalesced-ish stores
    *(float4*)&tr[warp][lane * 4] = acc;
    __syncthreads();

    float* ob = out + (size_t)b * C2 * NP + blockIdx.x * 8;
    for (int i = tid; i < C2 * 8; i += 256) {
        int si = i & 7;       // center within block
        int p  = i >> 3;      // channel
        ob[p * NP + si] = tr[si][p];
    }
}

extern "C" void kernel_launch(void* const* d_in, const int* in_sizes, int n_in,
                              void* d_out, int out_size)
{
    const float* x  = (const float*)d_in[0];
    const float* W1 = (const float*)d_in[1];
    const float* b1 = (const float*)d_in[2];
    const float* W2 = (const float*)d_in[3];
    const float* b2 = (const float*)d_in[4];
    float* out = (float*)d_out;

    // Kernel 1: one warp per point -> 16384 warps, 8 warps/block
    mlp_kernel<<<(NB * NP) / 8, 256>>>(x, W1, b1, W2, b2);

    // Kernel 2: 8 centers per block, grid (256, 8)
    dim3 grid(NP / 8, NB);
    group_max_kernel<<<grid, 256>>>(x, out);
}

// round 3
// speedup vs baseline: 5.0993x; 5.0993x over previous
#include <cuda_runtime.h>
#include <cuda_fp16.h>

#define NB   8
#define NP   2048
#define C1   64
#define C2   128
#define NS   64
#define RAD2 0.36f

// Scratch: per-point MLP features f[b, n, 128] in fp16 (4 MB, L2-resident)
__device__ __half g_fh[NB * NP * C2];

// ---------------------------------------------------------------------------
// Kernel 1: per-point MLP  f[p,:] = relu(W2 @ relu(W1 @ x[p] + b1) + b2)
// Block = 256 threads handles 128 points. W2 transposed into SMEM (k-major)
// so the warp's per-k weight read is ONE conflict-free LDS.128; h1 staged in
// SMEM and read via broadcast LDS.128. Warp processes 4 points concurrently
// (16 fp32 accumulators) -> FMA-pipe bound.
// ---------------------------------------------------------------------------
__global__ __launch_bounds__(256)
void mlp_kernel(const float* __restrict__ x,
                const float* __restrict__ W1,
                const float* __restrict__ b1,
                const float* __restrict__ W2,
                const float* __restrict__ b2)
{
    __shared__ float w2t[C1][C2];      // 32 KB, [k][p]
    __shared__ float h1s[128][C1];     // 32 KB
    __shared__ float xs3[128 * 3];
    __shared__ float b2s[C2];

    int tid = threadIdx.x;
    int p0  = blockIdx.x * 128;        // base point id for this block

    // Stage W2 transposed: w2t[k][p] = W2[p*64+k]
    for (int i = tid; i < C2 * C1; i += 256) {
        int p = i >> 6, k = i & 63;
        w2t[k][p] = W2[i];
    }
    for (int i = tid; i < 128 * 3; i += 256) xs3[i] = x[p0 * 3 + i];
    if (tid < C2) b2s[tid] = b2[tid];
    __syncthreads();

    // Phase 1: h1 for 128 points (8192 values / 256 threads = 32 each)
    for (int i = tid; i < 128 * C1; i += 256) {
        int q = i >> 6, c = i & 63;
        float v = fmaf(W1[c * 3 + 2], xs3[q * 3 + 2],
                  fmaf(W1[c * 3 + 1], xs3[q * 3 + 1],
                  fmaf(W1[c * 3 + 0], xs3[q * 3 + 0], b1[c])));
        h1s[q][c] = fmaxf(v, 0.f);
    }
    __syncthreads();

    // Phase 2: warp w -> points [w*16, w*16+16), 4 groups of 4 points
    int warp = tid >> 5, lane = tid & 31;
    int lane4 = lane * 4;
    float4 binit = *(const float4*)&b2s[lane4];

#define ACC4(aa, hh) \
    aa.x = fmaf(hh, w.x, aa.x); aa.y = fmaf(hh, w.y, aa.y); \
    aa.z = fmaf(hh, w.z, aa.z); aa.w = fmaf(hh, w.w, aa.w);

    for (int g = 0; g < 4; g++) {
        int q = warp * 16 + g * 4;
        float4 a0 = binit, a1 = binit, a2 = binit, a3 = binit;

        #pragma unroll
        for (int k = 0; k < C1; k += 4) {
            float4 hv0 = *(const float4*)(h1s[q + 0] + k);
            float4 hv1 = *(const float4*)(h1s[q + 1] + k);
            float4 hv2 = *(const float4*)(h1s[q + 2] + k);
            float4 hv3 = *(const float4*)(h1s[q + 3] + k);
            float4 w;
            w = *(const float4*)(w2t[k + 0] + lane4);
            ACC4(a0, hv0.x) ACC4(a1, hv1.x) ACC4(a2, hv2.x) ACC4(a3, hv3.x)
            w = *(const float4*)(w2t[k + 1] + lane4);
            ACC4(a0, hv0.y) ACC4(a1, hv1.y) ACC4(a2, hv2.y) ACC4(a3, hv3.y)
            w = *(const float4*)(w2t[k + 2] + lane4);
            ACC4(a0, hv0.z) ACC4(a1, hv1.z) ACC4(a2, hv2.z) ACC4(a3, hv3.z)
            w = *(const float4*)(w2t[k + 3] + lane4);
            ACC4(a0, hv0.w) ACC4(a1, hv1.w) ACC4(a2, hv2.w) ACC4(a3, hv3.w)
        }

        // relu + convert to fp16 + store (8B per lane, coalesced 256B/point)
        float4 r[4] = {a0, a1, a2, a3};
        #pragma unroll
        for (int pt = 0; pt < 4; pt++) {
            float4 v = r[pt];
            __half2 h01 = __floats2half2_rn(fmaxf(v.x, 0.f), fmaxf(v.y, 0.f));
            __half2 h23 = __floats2half2_rn(fmaxf(v.z, 0.f), fmaxf(v.w, 0.f));
            uint2 st;
            st.x = *(unsigned*)&h01;
            st.y = *(unsigned*)&h23;
            ((uint2*)(g_fh + (size_t)(p0 + q + pt) * C2))[lane] = st;
        }
    }
#undef ACC4
}

// ---------------------------------------------------------------------------
// Kernel 2: ball query (first 64 in-radius indices, ascending) + max-pool of
// fp16 f. Block = 8 warps, 8 centers of one batch. x/sq staged in SMEM.
// Lane owns 4 channels (one uint2 = 4 halves per neighbor), __hmax2 reduce.
// ---------------------------------------------------------------------------
__global__ __launch_bounds__(256, 5)
void group_max_kernel(const float* __restrict__ x, float* __restrict__ out)
{
    __shared__ float xs[NP], ys[NP], zs[NP], sq[NP];     // 32 KB
    __shared__ unsigned short nbr[8][NS];                // 1 KB
    __shared__ float tr[8][132];                         // padded transpose buf

    int b   = blockIdx.y;
    int tid = threadIdx.x;

    const float* xb = x + b * NP * 3;
    for (int i = tid; i < NP; i += 256) {
        float a0 = xb[i * 3 + 0];
        float a1 = xb[i * 3 + 1];
        float a2 = xb[i * 3 + 2];
        xs[i] = a0; ys[i] = a1; zs[i] = a2;
        sq[i] = a0 * a0 + a1 * a1 + a2 * a2;
    }
    __syncthreads();

    int warp = tid >> 5, lane = tid & 31;
    int s = blockIdx.x * 8 + warp;

    float cx = xs[s], cy = ys[s], cz = zs[s], cs = sq[s];

    // Scan ascending j; first <=64 with dist <= R^2
    int cnt = 0;
    for (int j0 = 0; j0 < NP && cnt < NS; j0 += 32) {
        int j = j0 + lane;
        float d = cs + sq[j] - 2.f * (cx * xs[j] + cy * ys[j] + cz * zs[j]);
        bool ok = !(d > RAD2);
        unsigned mask = __ballot_sync(0xffffffffu, ok);
        int rank = __popc(mask & ((1u << lane) - 1u));
        if (ok && (cnt + rank) < NS)
            nbr[warp][cnt + rank] = (unsigned short)j;
        cnt += __popc(mask);
        if (cnt > NS) cnt = NS;
    }
    __syncwarp();

    // Max-pool fp16 f over neighbors: lane owns channels 4*lane..4*lane+3
    const uint2* fb = (const uint2*)(g_fh + (size_t)b * NP * C2);  // 32 uint2 per point
    __half2 m0 = __float2half2_rn(0.f);
    __half2 m1 = m0;

    int k = 0;
    for (; k + 8 <= cnt; k += 8) {
        uint2 v[8];
        #pragma unroll
        for (int u = 0; u < 8; u++)
            v[u] = fb[(int)nbr[warp][k + u] * 32 + lane];
        #pragma unroll
        for (int u = 0; u < 8; u++) {
            m0 = __hmax2(m0, *reinterpret_cast<__half2*>(&v[u].x));
            m1 = __hmax2(m1, *reinterpret_cast<__half2*>(&v[u].y));
        }
    }
    for (; k < cnt; k++) {
        uint2 v = fb[(int)nbr[warp][k] * 32 + lane];
        m0 = __hmax2(m0, *reinterpret_cast<__half2*>(&v.x));
        m1 = __hmax2(m1, *reinterpret_cast<__half2*>(&v.y));
    }

    float2 f0 = __half22float2(m0);
    float2 f1 = __half22float2(m1);
    tr[warp][lane * 4 + 0] = f0.x;
    tr[warp][lane * 4 + 1] = f0.y;
    tr[warp][lane * 4 + 2] = f1.x;
    tr[warp][lane * 4 + 3] = f1.y;
    __syncthreads();

    float* ob = out + (size_t)b * C2 * NP + blockIdx.x * 8;
    for (int i = tid; i < C2 * 8; i += 256) {
        int si = i & 7;       // center within block
        int p  = i >> 3;      // channel
        ob[p * NP + si] = tr[si][p];
    }
}

extern "C" void kernel_launch(void* const* d_in, const int* in_sizes, int n_in,
                              void* d_out, int out_size)
{
    const float* x  = (const float*)d_in[0];
    const float* W1 = (const float*)d_in[1];
    const float* b1 = (const float*)d_in[2];
    const float* W2 = (const float*)d_in[3];
    const float* b2 = (const float*)d_in[4];
    float* out = (float*)d_out;

    // Kernel 1: 128 points per block -> 128 blocks (one wave)
    mlp_kernel<<<(NB * NP) / 128, 256>>>(x, W1, b1, W2, b2);

    // Kernel 2: 8 centers per block, grid (256, 8)
    dim3 grid(NP / 8, NB);
    group_max_kernel<<<grid, 256>>>(x, out);
}